// round 10
// baseline (speedup 1.0000x reference)
#include <cuda_runtime.h>

// Problem constants (fixed shapes)
#define BATCH   2
#define H       64
#define W       64
#define C       128
#define N_IN    (H * W * C)            // 524288
#define N_POOL  ((H/2) * (W/2) * C)    // 131072
#define N_OUT   32

// Output layout (concatenated, all float32):
//   [0, OFF1)       w_zero #1 : 33,554,432
//   [OFF1, OFF2)    b_out_u_  : 64
//   [OFF2, OFF3)    w_zero #2 : 33,554,432
//   [OFF3, TOTAL)   b_out_l_  : 64
#define OFF1    (BATCH * N_IN * N_OUT)         // 33554432
#define OFF2    (OFF1 + BATCH * N_OUT)         // 33554496
#define OFF3    (OFF2 + BATCH * N_IN * N_OUT)  // 67108928
#define TOTAL   (OFF3 + BATCH * N_OUT)         // 67108992

#define NTHREADS 256
#define RGRID    2048                          // one 2x2 pool window per block

// ---------------------------------------------------------------------------
// Seed the two bias slots with the input biases (after the memset; the
// reduce kernel's atomicAdds accumulate onto these).
// ---------------------------------------------------------------------------
__global__ void init_bias_kernel(float* __restrict__ out,
                                 const float* __restrict__ b_out_u,
                                 const float* __restrict__ b_out_l) {
    const int i = threadIdx.x;                 // 0..63
    if (i < BATCH * N_OUT) {
        out[OFF1 + i] = b_out_u[i];
        out[OFF3 + i] = b_out_l[i];
    }
}

__device__ __forceinline__ float4 ldcs4(const float* p) {
    return __ldcs(reinterpret_cast<const float4*>(p));
}

// ---------------------------------------------------------------------------
// Fused pool + sign-split dot, barrier-free main path.
//   bm = (bu+bl)/2, bd = (bu-bl)/2
//   upper: w*bm + |w|*bd      lower: w*bm - |w|*bd
// Weight LDG.128s are issued FIRST; each warp then computes its own 16
// channels' bounds with coalesced loads + shfl (no smem, no __syncthreads),
// fully overlapped with the in-flight weight loads.
// ---------------------------------------------------------------------------
__global__ void __launch_bounds__(NTHREADS)
reduce_kernel(float* __restrict__ out,
              const float* __restrict__ u_c,
              const float* __restrict__ l_c,
              const float* __restrict__ w_out_u,
              const float* __restrict__ w_out_l) {
    const int t    = threadIdx.x;
    const int bIdx = blockIdx.x;
    const int b    = bIdx >> 10;               // 1024 windows per batch
    const int widx = bIdx & 1023;
    const int oh   = widx >> 5;
    const int ow   = widx & 31;
    const int base0 = b * N_IN + oh * (2 * W * C) + ow * (2 * C);

    const int warp    = t >> 5;
    const int lane    = t & 31;
    const int row_sub = lane >> 3;             // 0..3
    const int oq      = lane & 7;              // 0..7

    // ---- issue all 8 weight loads first (no dependencies) ----
    float4 WU[4], WL[4];
    {
        const size_t rbase = (size_t)(bIdx * 128 + warp * 16 + row_sub) * N_OUT + oq * 4;
        #pragma unroll
        for (int j = 0; j < 4; j++)
            WU[j] = ldcs4(w_out_u + rbase + (size_t)j * 4 * N_OUT);
        #pragma unroll
        for (int j = 0; j < 4; j++)
            WL[j] = ldcs4(w_out_l + rbase + (size_t)j * 4 * N_OUT);
    }

    // ---- per-warp bounds for this warp's 16 channels (overlapped) ----
    // lane l: channel c = warp*16 + (l&15); half h = l>>4 picks window column.
    // Each lane loads rows (0,h) and (1,h) of the 2x2 window; shfl_xor(16)
    // combines the two columns. Lanes 0-15 and 16-31 both end with bu/bl.
    float bm, bd;
    {
        const int lo16 = lane & 15;
        const int h    = lane >> 4;            // 0 or 1
        const int ia = base0 + h * C + warp * 16 + lo16;          // row 0
        const int ib = ia + W * C;                                // row 1
        const float ua = __ldg(u_c + ia);
        const float ub = __ldg(u_c + ib);
        const float la = __ldg(l_c + ia);
        const float lb = __ldg(l_c + ib);
        float um = fmaxf(ua, ub);
        float lm = fmaxf(la, lb);
        um = fmaxf(um, __shfl_xor_sync(0xFFFFFFFFu, um, 16));
        lm = fmaxf(lm, __shfl_xor_sync(0xFFFFFFFFu, lm, 16));
        bm = 0.5f * (um + lm);
        bd = 0.5f * (um - lm);
        // lane l now holds bm/bd for local channel (l & 15)
    }

    // ---- compute: 2 FFMA per weight element ----
    float4 au1 = make_float4(0.f, 0.f, 0.f, 0.f);
    float4 au2 = make_float4(0.f, 0.f, 0.f, 0.f);
    float4 al1 = make_float4(0.f, 0.f, 0.f, 0.f);
    float4 al2 = make_float4(0.f, 0.f, 0.f, 0.f);

    #pragma unroll
    for (int j = 0; j < 4; j++) {
        const int src = j * 4 + row_sub;       // local channel for this lane
        const float bmj = __shfl_sync(0xFFFFFFFFu, bm, src);
        const float bdj = __shfl_sync(0xFFFFFFFFu, bd, src);
        const float4 wu = WU[j];
        const float4 wl = WL[j];

        au1.x += wu.x * bmj;  au2.x += fabsf(wu.x) * bdj;
        au1.y += wu.y * bmj;  au2.y += fabsf(wu.y) * bdj;
        au1.z += wu.z * bmj;  au2.z += fabsf(wu.z) * bdj;
        au1.w += wu.w * bmj;  au2.w += fabsf(wu.w) * bdj;

        al1.x += wl.x * bmj;  al2.x += fabsf(wl.x) * bdj;
        al1.y += wl.y * bmj;  al2.y += fabsf(wl.y) * bdj;
        al1.z += wl.z * bmj;  al2.z += fabsf(wl.z) * bdj;
        al1.w += wl.w * bmj;  al2.w += fabsf(wl.w) * bdj;
    }

    float4 accu = make_float4(au1.x + au2.x, au1.y + au2.y,
                              au1.z + au2.z, au1.w + au2.w);
    float4 accl = make_float4(al1.x - al2.x, al1.y - al2.y,
                              al1.z - al2.z, al1.w - al2.w);

    // reduce across row_sub (lane bits 3,4)
    #pragma unroll
    for (int d = 8; d < 32; d <<= 1) {
        accu.x += __shfl_xor_sync(0xFFFFFFFFu, accu.x, d);
        accu.y += __shfl_xor_sync(0xFFFFFFFFu, accu.y, d);
        accu.z += __shfl_xor_sync(0xFFFFFFFFu, accu.z, d);
        accu.w += __shfl_xor_sync(0xFFFFFFFFu, accu.w, d);
        accl.x += __shfl_xor_sync(0xFFFFFFFFu, accl.x, d);
        accl.y += __shfl_xor_sync(0xFFFFFFFFu, accl.y, d);
        accl.z += __shfl_xor_sync(0xFFFFFFFFu, accl.z, d);
        accl.w += __shfl_xor_sync(0xFFFFFFFFu, accl.w, d);
    }

    __shared__ float4 su[8][8];                // [warp][oq]
    __shared__ float4 sl[8][8];
    if (row_sub == 0) {
        su[warp][oq] = accu;
        sl[warp][oq] = accl;
    }
    __syncthreads();

    // block reduction over 8 warps, then 64 atomicAdds to bias slots
    if (warp == 0) {
        const int o = lane;
        const float* p = reinterpret_cast<const float*>(&su[0][0]) + (o >> 2) * 4 + (o & 3);
        float s = 0.f;
        #pragma unroll
        for (int k = 0; k < 8; k++) s += p[k * 32];
        atomicAdd(&out[OFF1 + b * N_OUT + o], s);
    } else if (warp == 1) {
        const int o = lane;
        const float* p = reinterpret_cast<const float*>(&sl[0][0]) + (o >> 2) * 4 + (o & 3);
        float s = 0.f;
        #pragma unroll
        for (int k = 0; k < 8; k++) s += p[k * 32];
        atomicAdd(&out[OFF3 + b * N_OUT + o], s);
    }
}

extern "C" void kernel_launch(void* const* d_in, const int* in_sizes, int n_in,
                              void* d_out, int out_size) {
    // metadata order: y, x_0, u_c, l_c, w_out_u, b_out_u, w_out_l, b_out_l
    const float* u_c     = (const float*)d_in[2];
    const float* l_c     = (const float*)d_in[3];
    const float* w_out_u = (const float*)d_in[4];
    const float* b_out_u = (const float*)d_in[5];
    const float* w_out_l = (const float*)d_in[6];
    const float* b_out_l = (const float*)d_in[7];
    float* out = (float*)d_out;

    // Phase 1: driver zero fill (at the ~5 TB/s store ceiling).
    cudaMemsetAsync(out, 0, (size_t)TOTAL * sizeof(float));
    // Phase 2: seed bias slots.
    init_bias_kernel<<<1, 64>>>(out, b_out_u, b_out_l);
    // Phase 3: barrier-free fused pool + sign-split reduction.
    reduce_kernel<<<RGRID, NTHREADS>>>(out, u_c, l_c, w_out_u, w_out_l);
}